// round 2
// baseline (speedup 1.0000x reference)
#include <cuda_runtime.h>
#include <cuda_bf16.h>

#define NN 100000
#define NE 1200000

// ---------------- device scratch (no allocations allowed) ----------------
__device__ int   g_is64;           // edge_index dtype flag (1 = int64, 0 = int32)
__device__ int   g_cnt[NN];        // in-degree (edges only)
__device__ int   g_cur[NN];        // scatter cursors
__device__ float g_dinv[NN];       // rsqrt(deg), deg = in-degree + 1 (self loop)
__device__ int   g_rowptr[NN + 1]; // CSR row pointers (dst-major)
__device__ int   g_col[NE];        // CSR column = src node
__device__ float g_enorm[NE];      // per-edge norm = dinv[src]*dinv[dst]
__device__ float g_buf1[NN * 64];  // h @ W scratch
__device__ float g_buf2[NN * 64];  // aggregated hidden state

// ---------------- dtype probe ----------------
__global__ void k_detect(const int* __restrict__ raw) {
    // If the buffer is int64 (little-endian, values in [0, NN)), every odd
    // 32-bit word of the first 128 values is 0 and every even word < NN.
    bool ok64 = true;
    for (int i = 0; i < 128; i++) {
        if (raw[2 * i + 1] != 0) { ok64 = false; break; }
        unsigned v = (unsigned)raw[2 * i];
        if (v >= NN) { ok64 = false; break; }
    }
    g_is64 = ok64 ? 1 : 0;
}

__device__ __forceinline__ int edge_at(const int* raw, int idx, int is64) {
    if (is64) return (int)((const long long*)raw)[idx];
    return raw[idx];
}

// ---------------- CSR build ----------------
__global__ void k_init() {
    int i = blockIdx.x * blockDim.x + threadIdx.x;
    if (i < NN) { g_cnt[i] = 0; g_cur[i] = 0; }
}

__global__ void k_count(const int* __restrict__ raw) {
    int e = blockIdx.x * blockDim.x + threadIdx.x;
    if (e >= NE) return;
    int d = edge_at(raw, NE + e, g_is64);
    if ((unsigned)d < NN) atomicAdd(&g_cnt[d], 1);
}

__global__ void k_dinv() {
    int i = blockIdx.x * blockDim.x + threadIdx.x;
    if (i < NN) g_dinv[i] = rsqrtf((float)g_cnt[i] + 1.0f);
}

// single-block exclusive scan of g_cnt -> g_rowptr
__global__ void k_scan() {
    __shared__ int sums[1024];
    int tid = threadIdx.x;
    const int CH = (NN + 1023) / 1024;   // 98
    int beg = tid * CH;
    int end = min(beg + CH, NN);
    int s = 0;
    for (int i = beg; i < end; i++) s += g_cnt[i];
    sums[tid] = s;
    __syncthreads();
    for (int d = 1; d < 1024; d <<= 1) {
        int v = (tid >= d) ? sums[tid - d] : 0;
        __syncthreads();
        sums[tid] += v;
        __syncthreads();
    }
    int off = (tid == 0) ? 0 : sums[tid - 1];
    for (int i = beg; i < end; i++) { g_rowptr[i] = off; off += g_cnt[i]; }
    if (tid == 0) g_rowptr[NN] = NE;
}

__global__ void k_fill(const int* __restrict__ raw) {
    int e = blockIdx.x * blockDim.x + threadIdx.x;
    if (e >= NE) return;
    int is64 = g_is64;
    int s = edge_at(raw, e, is64);
    int d = edge_at(raw, NE + e, is64);
    if ((unsigned)s >= NN || (unsigned)d >= NN) return;
    int pos = g_rowptr[d] + atomicAdd(&g_cur[d], 1);
    g_col[pos]   = s;
    g_enorm[pos] = g_dinv[s] * g_dinv[d];
}

// ---------------- dense GEMM: out[N,NC] = in[N,64] @ W[64,NC] (+bias) ----------------
template <int NC, bool BIAS>
__global__ void k_gemm(const float* __restrict__ in, const float* __restrict__ W,
                       const float* __restrict__ bias, float* __restrict__ out) {
    constexpr int CG = NC / 4;       // col groups of 4
    constexpr int RT = 256 / CG;     // thread-row groups
    constexpr int TM = RT * 4;       // rows per tile
    constexpr int XP = 65;           // padded x row (bank-conflict-free)
    __shared__ float Ws[64 * NC];
    __shared__ float Xs[TM * XP];

    for (int i = threadIdx.x; i < 64 * NC; i += 256) Ws[i] = W[i];

    int rq = threadIdx.x / CG;
    int cg = threadIdx.x % CG;
    int ntiles = (NN + TM - 1) / TM;

    for (int tile = blockIdx.x; tile < ntiles; tile += gridDim.x) {
        int row0 = tile * TM;
        int nr = min(TM, NN - row0);
        __syncthreads();
        for (int i = threadIdx.x; i < nr * 64; i += 256)
            Xs[(i >> 6) * XP + (i & 63)] = in[row0 * 64 + i];
        __syncthreads();

        float acc[4][4] = {};
#pragma unroll
        for (int k = 0; k < 64; k++) {
            float4 w4 = *(const float4*)&Ws[k * NC + cg * 4];
#pragma unroll
            for (int r = 0; r < 4; r++) {
                float xv = Xs[(rq * 4 + r) * XP + k];
                acc[r][0] += xv * w4.x;
                acc[r][1] += xv * w4.y;
                acc[r][2] += xv * w4.z;
                acc[r][3] += xv * w4.w;
            }
        }
        float4 bv = make_float4(0.f, 0.f, 0.f, 0.f);
        if (BIAS) bv = *(const float4*)&bias[cg * 4];
#pragma unroll
        for (int r = 0; r < 4; r++) {
            int row = row0 + rq * 4 + r;
            if (row < NN) {
                float4 o = make_float4(acc[r][0] + bv.x, acc[r][1] + bv.y,
                                       acc[r][2] + bv.z, acc[r][3] + bv.w);
                *(float4*)&out[row * NC + cg * 4] = o;
            }
        }
    }
}

// ---------------- aggregate: out[i] = relu( sum_e norm*hw[src] + dinv[i]^2*hw[i] + b ) ----------------
__global__ void k_gather(const float* __restrict__ hw, const float* __restrict__ bias,
                         float* __restrict__ hout) {
    int node = blockIdx.x * (blockDim.x >> 5) + (threadIdx.x >> 5);
    if (node >= NN) return;
    int lane = threadIdx.x & 31;
    const float2* __restrict__ hw2 = (const float2*)hw;

    float di = g_dinv[node];
    float self = di * di;
    float2 v = hw2[node * 32 + lane];
    float ax = self * v.x, ay = self * v.y;

    int beg = g_rowptr[node], end = g_rowptr[node + 1];
    int j = beg;
    for (; j + 1 < end; j += 2) {
        int c0 = g_col[j], c1 = g_col[j + 1];
        float w0 = g_enorm[j], w1 = g_enorm[j + 1];
        float2 u0 = __ldg(&hw2[c0 * 32 + lane]);
        float2 u1 = __ldg(&hw2[c1 * 32 + lane]);
        ax += w0 * u0.x; ay += w0 * u0.y;
        ax += w1 * u1.x; ay += w1 * u1.y;
    }
    if (j < end) {
        int c = g_col[j];
        float w = g_enorm[j];
        float2 u = __ldg(&hw2[c * 32 + lane]);
        ax += w * u.x; ay += w * u.y;
    }
    float2 b = ((const float2*)bias)[lane];
    ax = fmaxf(ax + b.x, 0.f);
    ay = fmaxf(ay + b.y, 0.f);
    ((float2*)hout)[node * 32 + lane] = make_float2(ax, ay);
}

// ---------------- launch ----------------
extern "C" void kernel_launch(void* const* d_in, const int* in_sizes, int n_in,
                              void* d_out, int out_size) {
    const float* x  = (const float*)d_in[0];
    const int*   ei = (const int*)d_in[1];   // raw words; dtype resolved on device
    const float* W1 = (const float*)d_in[2];
    const float* b1 = (const float*)d_in[3];
    const float* W2 = (const float*)d_in[4];
    const float* b2 = (const float*)d_in[5];
    const float* Wl = (const float*)d_in[6];
    const float* bl = (const float*)d_in[7];
    float*       out = (float*)d_out;

    float* buf1; cudaGetSymbolAddress((void**)&buf1, g_buf1);
    float* buf2; cudaGetSymbolAddress((void**)&buf2, g_buf2);

    const int TB = 256;
    int gN = (NN + TB - 1) / TB;
    int gE = (NE + TB - 1) / TB;

    // CSR build (per launch; edges are an input)
    k_detect<<<1, 1>>>(ei);
    k_init<<<gN, TB>>>();
    k_count<<<gE, TB>>>(ei);
    k_dinv<<<gN, TB>>>();
    k_scan<<<1, 1024>>>();
    k_fill<<<gE, TB>>>(ei);

    const int GEMM_GRID = 296;   // 2 blocks per SM

    // layer 1
    k_gemm<64, false><<<GEMM_GRID, 256>>>(x, W1, nullptr, buf1);
    k_gather<<<(NN + 7) / 8, 256>>>(buf1, b1, buf2);
    // layer 2
    k_gemm<64, false><<<GEMM_GRID, 256>>>(buf2, W2, nullptr, buf1);
    k_gather<<<(NN + 7) / 8, 256>>>(buf1, b2, buf2);
    // output projection
    k_gemm<32, true><<<GEMM_GRID, 256>>>(buf2, Wl, bl, out);
}

// round 3
// speedup vs baseline: 1.5433x; 1.5433x over previous
#include <cuda_runtime.h>
#include <cuda_fp16.h>

#define NN 100000
#define NE 1200000
#define SCAN_B 98   // ceil(NN / 1024)

// ---------------- device scratch (no allocations allowed) ----------------
__device__ int    g_is64;
__device__ int    g_cnt[NN];
__device__ int    g_cur[NN];         // scatter cursors (seeded with rowptr)
__device__ float  g_dinv[NN];
__device__ int    g_rowptr[NN + 1];
__device__ int2   g_edge[NE];        // {src, norm-as-int}
__device__ int    g_bsum[SCAN_B];
__device__ int    g_boff[SCAN_B];
__device__ __half g_bufh[NN * 64];   // h @ W in fp16 (gather operand)
__device__ float  g_buf2[NN * 64];   // aggregated hidden state (fp32)

// packed f32x2 FMA (sm_103a FFMA2; 2x fp32 FMA throughput)
#define FMA_F32X2(d, a, b, c) \
    asm("fma.rn.f32x2 %0, %1, %2, %3;" : "=l"(d) : "l"(a), "l"(b), "l"(c))
#define PACK_F32X2(out, lo, hi) \
    asm("mov.b64 %0, {%1, %2};" : "=l"(out) : "f"(lo), "f"(hi))
#define UNPACK_F32X2(lo, hi, in) \
    asm("mov.b64 {%0, %1}, %2;" : "=f"(lo), "=f"(hi) : "l"(in))

// ---------------- dtype probe ----------------
__global__ void k_detect(const int* __restrict__ raw) {
    bool ok64 = true;
    for (int i = 0; i < 128; i++) {
        if (raw[2 * i + 1] != 0) { ok64 = false; break; }
        if ((unsigned)raw[2 * i] >= NN) { ok64 = false; break; }
    }
    g_is64 = ok64 ? 1 : 0;
}

__device__ __forceinline__ int edge_at(const int* raw, int idx, int is64) {
    return is64 ? (int)((const long long*)raw)[idx] : raw[idx];
}

// ---------------- CSR build ----------------
__global__ void k_init() {
    int i = blockIdx.x * blockDim.x + threadIdx.x;
    if (i < NN) g_cnt[i] = 0;
}

__global__ void k_count(const int* __restrict__ raw) {
    int e = blockIdx.x * blockDim.x + threadIdx.x;
    if (e >= NE) return;
    int d = edge_at(raw, NE + e, g_is64);
    if ((unsigned)d < NN) atomicAdd(&g_cnt[d], 1);
}

// phase 1: per-block sums (coalesced) + fused dinv
__global__ void k_scan1() {
    __shared__ int red[32];
    int i = blockIdx.x * 1024 + threadIdx.x;
    int c = (i < NN) ? g_cnt[i] : 0;
    if (i < NN) g_dinv[i] = rsqrtf((float)c + 1.0f);
    int v = c;
#pragma unroll
    for (int o = 16; o; o >>= 1) v += __shfl_down_sync(~0u, v, o);
    if ((threadIdx.x & 31) == 0) red[threadIdx.x >> 5] = v;
    __syncthreads();
    if (threadIdx.x < 32) {
        int w = red[threadIdx.x];
#pragma unroll
        for (int o = 16; o; o >>= 1) w += __shfl_down_sync(~0u, w, o);
        if (threadIdx.x == 0) g_bsum[blockIdx.x] = w;
    }
}

// phase 2: scan the 98 block sums
__global__ void k_scan2() {
    __shared__ int s[128];
    int tid = threadIdx.x;
    int v = (tid < SCAN_B) ? g_bsum[tid] : 0;
    s[tid] = v;
    __syncthreads();
    for (int d = 1; d < 128; d <<= 1) {
        int t = (tid >= d) ? s[tid - d] : 0;
        __syncthreads();
        s[tid] += t;
        __syncthreads();
    }
    if (tid < SCAN_B) g_boff[tid] = s[tid] - v;   // exclusive
    if (tid == 0) g_rowptr[NN] = NE;
}

// phase 3: block-local exclusive scan + offset -> rowptr & cursor seed
__global__ void k_scan3() {
    __shared__ int wsum[32];
    int tid = threadIdx.x;
    int lane = tid & 31, wid = tid >> 5;
    int i = blockIdx.x * 1024 + tid;
    int c = (i < NN) ? g_cnt[i] : 0;
    int incl = c;
#pragma unroll
    for (int o = 1; o < 32; o <<= 1) {
        int t = __shfl_up_sync(~0u, incl, o);
        if (lane >= o) incl += t;
    }
    if (lane == 31) wsum[wid] = incl;
    __syncthreads();
    if (tid < 32) {
        int w = wsum[tid];
        int iw = w;
#pragma unroll
        for (int o = 1; o < 32; o <<= 1) {
            int t = __shfl_up_sync(~0u, iw, o);
            if (tid >= o) iw += t;
        }
        wsum[tid] = iw - w;   // exclusive warp prefix
    }
    __syncthreads();
    if (i < NN) {
        int excl = incl - c + wsum[wid] + g_boff[blockIdx.x];
        g_rowptr[i] = excl;
        g_cur[i] = excl;
    }
}

__global__ void k_fill(const int* __restrict__ raw) {
    int e = blockIdx.x * blockDim.x + threadIdx.x;
    if (e >= NE) return;
    int is64 = g_is64;
    int s = edge_at(raw, e, is64);
    int d = edge_at(raw, NE + e, is64);
    if ((unsigned)s >= NN || (unsigned)d >= NN) return;
    int pos = atomicAdd(&g_cur[d], 1);
    g_edge[pos] = make_int2(s, __float_as_int(g_dinv[s] * g_dinv[d]));
}

// ---------------- GEMM epilogue stores ----------------
__device__ __forceinline__ void store4(float* p, float a, float b, float c, float d) {
    *(float4*)p = make_float4(a, b, c, d);
}
__device__ __forceinline__ void store4(__half* p, float a, float b, float c, float d) {
    *(__half2*)p = __floats2half2_rn(a, b);
    *(__half2*)(p + 2) = __floats2half2_rn(c, d);
}

// ---------------- dense GEMM: out[N,NC] = in[N,64] @ W[64,NC] (+bias) ----------------
// f32x2 packed FMA: W column-pairs come pre-packed from shared memory.
template <int NC, typename OutT, bool BIAS>
__global__ void __launch_bounds__(256) k_gemm(const float* __restrict__ in,
                                              const float* __restrict__ W,
                                              const float* __restrict__ bias,
                                              OutT* __restrict__ out) {
    constexpr int CG = NC / 4;       // col groups of 4
    constexpr int RQ = 256 / CG;     // row groups
    constexpr int TM = RQ * 4;       // rows per tile
    constexpr int XP = 65;
    __shared__ float Ws[64 * NC];
    __shared__ float Xs[TM * XP];

    for (int i = threadIdx.x; i < 64 * NC; i += 256) Ws[i] = W[i];

    int rq = threadIdx.x / CG;
    int cg = threadIdx.x % CG;
    int ntiles = (NN + TM - 1) / TM;

    for (int tile = blockIdx.x; tile < ntiles; tile += gridDim.x) {
        int row0 = tile * TM;
        int nr = min(TM, NN - row0);
        __syncthreads();
        for (int i = threadIdx.x; i < nr * 64; i += 256)
            Xs[(i >> 6) * XP + (i & 63)] = in[row0 * 64 + i];
        __syncthreads();

        unsigned long long acc[4][2] = {};
#pragma unroll 4
        for (int k = 0; k < 64; k++) {
            ulonglong2 w = *(const ulonglong2*)&Ws[k * NC + cg * 4];
#pragma unroll
            for (int r = 0; r < 4; r++) {
                float xv = Xs[(rq * 4 + r) * XP + k];
                unsigned long long xx;
                PACK_F32X2(xx, xv, xv);
                FMA_F32X2(acc[r][0], xx, w.x, acc[r][0]);
                FMA_F32X2(acc[r][1], xx, w.y, acc[r][1]);
            }
        }
        float4 bv = make_float4(0.f, 0.f, 0.f, 0.f);
        if (BIAS) bv = *(const float4*)&bias[cg * 4];
#pragma unroll
        for (int r = 0; r < 4; r++) {
            int row = row0 + rq * 4 + r;
            if (row < NN) {
                float f0, f1, f2, f3;
                UNPACK_F32X2(f0, f1, acc[r][0]);
                UNPACK_F32X2(f2, f3, acc[r][1]);
                store4(&out[row * NC + cg * 4],
                       f0 + bv.x, f1 + bv.y, f2 + bv.z, f3 + bv.w);
            }
        }
    }
}

// ---------------- aggregate: out[i] = relu( sum_e norm*hw[src] + dinv^2*hw[i] + b ) ----------------
__global__ void __launch_bounds__(256) k_gather(const __half2* __restrict__ hw,
                                                const float* __restrict__ bias,
                                                float* __restrict__ hout) {
    int node = blockIdx.x * 8 + (threadIdx.x >> 5);
    if (node >= NN) return;
    int lane = threadIdx.x & 31;

    float di = g_dinv[node];
    float self = di * di;
    float2 v = __half22float2(__ldg(&hw[node * 32 + lane]));
    float ax = self * v.x, ay = self * v.y;

    int beg = g_rowptr[node], end = g_rowptr[node + 1];
    int j = beg;
    for (; j + 4 <= end; j += 4) {
        int2 e0 = __ldg(&g_edge[j]);
        int2 e1 = __ldg(&g_edge[j + 1]);
        int2 e2 = __ldg(&g_edge[j + 2]);
        int2 e3 = __ldg(&g_edge[j + 3]);
        float2 u0 = __half22float2(__ldg(&hw[e0.x * 32 + lane]));
        float2 u1 = __half22float2(__ldg(&hw[e1.x * 32 + lane]));
        float2 u2 = __half22float2(__ldg(&hw[e2.x * 32 + lane]));
        float2 u3 = __half22float2(__ldg(&hw[e3.x * 32 + lane]));
        float w0 = __int_as_float(e0.y), w1 = __int_as_float(e1.y);
        float w2 = __int_as_float(e2.y), w3 = __int_as_float(e3.y);
        ax = fmaf(w0, u0.x, ax); ay = fmaf(w0, u0.y, ay);
        ax = fmaf(w1, u1.x, ax); ay = fmaf(w1, u1.y, ay);
        ax = fmaf(w2, u2.x, ax); ay = fmaf(w2, u2.y, ay);
        ax = fmaf(w3, u3.x, ax); ay = fmaf(w3, u3.y, ay);
    }
    for (; j < end; j++) {
        int2 e = __ldg(&g_edge[j]);
        float2 u = __half22float2(__ldg(&hw[e.x * 32 + lane]));
        float w = __int_as_float(e.y);
        ax = fmaf(w, u.x, ax); ay = fmaf(w, u.y, ay);
    }
    float2 b = ((const float2*)bias)[lane];
    ax = fmaxf(ax + b.x, 0.f);
    ay = fmaxf(ay + b.y, 0.f);
    ((float2*)hout)[node * 32 + lane] = make_float2(ax, ay);
}

// ---------------- launch ----------------
extern "C" void kernel_launch(void* const* d_in, const int* in_sizes, int n_in,
                              void* d_out, int out_size) {
    const float* x  = (const float*)d_in[0];
    const int*   ei = (const int*)d_in[1];
    const float* W1 = (const float*)d_in[2];
    const float* b1 = (const float*)d_in[3];
    const float* W2 = (const float*)d_in[4];
    const float* b2 = (const float*)d_in[5];
    const float* Wl = (const float*)d_in[6];
    const float* bl = (const float*)d_in[7];
    float*       out = (float*)d_out;

    __half* bufh; cudaGetSymbolAddress((void**)&bufh, g_bufh);
    float*  buf2; cudaGetSymbolAddress((void**)&buf2, g_buf2);

    const int TB = 256;
    int gN = (NN + TB - 1) / TB;
    int gE = (NE + TB - 1) / TB;

    k_detect<<<1, 1>>>(ei);
    k_init<<<gN, TB>>>();
    k_count<<<gE, TB>>>(ei);
    k_scan1<<<SCAN_B, 1024>>>();
    k_scan2<<<1, 128>>>();
    k_scan3<<<SCAN_B, 1024>>>();
    k_fill<<<gE, TB>>>(ei);

    const int GEMM_GRID = 296;
    const int GATHER_GRID = (NN + 7) / 8;

    // layer 1
    k_gemm<64, __half, false><<<GEMM_GRID, 256>>>(x, W1, nullptr, bufh);
    k_gather<<<GATHER_GRID, 256>>>((const __half2*)bufh, b1, buf2);
    // layer 2
    k_gemm<64, __half, false><<<GEMM_GRID, 256>>>(buf2, W2, nullptr, bufh);
    k_gather<<<GATHER_GRID, 256>>>((const __half2*)bufh, b2, buf2);
    // output projection
    k_gemm<32, float, true><<<GEMM_GRID, 256>>>(buf2, Wl, bl, out);
}

// round 4
// speedup vs baseline: 1.7586x; 1.1395x over previous
#include <cuda_runtime.h>
#include <cuda_fp16.h>

#define NN 100000
#define NE 1200000
#define SCAN_B 98   // ceil(NN / 1024)

// ---------------- device scratch (no allocations allowed) ----------------
__device__ int    g_is64;
__device__ int    g_cnt[NN];
__device__ int    g_cur[NN];         // scatter cursors (seeded with rowptr)
__device__ float  g_dinv[NN];
__device__ int    g_rowptr[NN + 1];
__device__ int2   g_edge[NE];        // {src, norm-as-int}
__device__ int    g_bsum[SCAN_B];
__device__ __half g_bufh[NN * 64];   // h @ W (gather operand)
__device__ __half g_buf2[NN * 64];   // aggregated hidden state

// packed f32x2 FMA (sm_103a FFMA2; 2x fp32 FMA throughput)
#define FMA_F32X2(d, a, b, c) \
    asm("fma.rn.f32x2 %0, %1, %2, %3;" : "=l"(d) : "l"(a), "l"(b), "l"(c))
#define PACK_F32X2(out, lo, hi) \
    asm("mov.b64 %0, {%1, %2};" : "=l"(out) : "f"(lo), "f"(hi))
#define UNPACK_F32X2(lo, hi, in) \
    asm("mov.b64 {%0, %1}, %2;" : "=f"(lo), "=f"(hi) : "l"(in))

// ---------------- init + dtype probe (fused) ----------------
__global__ void k_initdetect(const int* __restrict__ raw) {
    int i = blockIdx.x * blockDim.x + threadIdx.x;
    if (i < NN) g_cnt[i] = 0;
    if (i == 0) {
        bool ok64 = true;
        for (int k = 0; k < 128; k++) {
            if (raw[2 * k + 1] != 0) { ok64 = false; break; }
            if ((unsigned)raw[2 * k] >= NN) { ok64 = false; break; }
        }
        g_is64 = ok64 ? 1 : 0;
    }
}

__device__ __forceinline__ int edge_at(const int* raw, int idx, int is64) {
    return is64 ? (int)((const long long*)raw)[idx] : raw[idx];
}

__global__ void k_count(const int* __restrict__ raw) {
    int e = blockIdx.x * blockDim.x + threadIdx.x;
    if (e >= NE) return;
    int d = edge_at(raw, NE + e, g_is64);
    if ((unsigned)d < NN) atomicAdd(&g_cnt[d], 1);
}

// phase 1: per-block sums (coalesced) + fused dinv
__global__ void k_scan1() {
    __shared__ int red[32];
    int i = blockIdx.x * 1024 + threadIdx.x;
    int c = (i < NN) ? g_cnt[i] : 0;
    if (i < NN) g_dinv[i] = rsqrtf((float)c + 1.0f);
    int v = c;
#pragma unroll
    for (int o = 16; o; o >>= 1) v += __shfl_down_sync(~0u, v, o);
    if ((threadIdx.x & 31) == 0) red[threadIdx.x >> 5] = v;
    __syncthreads();
    if (threadIdx.x < 32) {
        int w = red[threadIdx.x];
#pragma unroll
        for (int o = 16; o; o >>= 1) w += __shfl_down_sync(~0u, w, o);
        if (threadIdx.x == 0) g_bsum[blockIdx.x] = w;
    }
}

// phase 2+3 fused: every block redundantly scans the 98 block sums (cheap),
// then does its block-local exclusive scan -> rowptr & cursor seed.
__global__ void k_scan23() {
    __shared__ int bs[128];
    __shared__ int wsum[32];
    int tid = threadIdx.x;
    if (tid < 128) bs[tid] = (tid < SCAN_B) ? g_bsum[tid] : 0;
    __syncthreads();
    for (int d = 1; d < 128; d <<= 1) {
        int t = (tid < 128 && tid >= d) ? bs[tid - d] : 0;
        __syncthreads();
        if (tid < 128) bs[tid] += t;
        __syncthreads();
    }
    int boff = (blockIdx.x == 0) ? 0 : bs[blockIdx.x - 1];

    int lane = tid & 31, wid = tid >> 5;
    int i = blockIdx.x * 1024 + tid;
    int c = (i < NN) ? g_cnt[i] : 0;
    int incl = c;
#pragma unroll
    for (int o = 1; o < 32; o <<= 1) {
        int t = __shfl_up_sync(~0u, incl, o);
        if (lane >= o) incl += t;
    }
    if (lane == 31) wsum[wid] = incl;
    __syncthreads();
    if (tid < 32) {
        int w = wsum[tid];
        int iw = w;
#pragma unroll
        for (int o = 1; o < 32; o <<= 1) {
            int t = __shfl_up_sync(~0u, iw, o);
            if (tid >= o) iw += t;
        }
        wsum[tid] = iw - w;
    }
    __syncthreads();
    if (i < NN) {
        int excl = incl - c + wsum[wid] + boff;
        g_rowptr[i] = excl;
        g_cur[i] = excl;
    }
    if (blockIdx.x == 0 && tid == 0) g_rowptr[NN] = NE;
}

__global__ void k_fill(const int* __restrict__ raw) {
    int e = blockIdx.x * blockDim.x + threadIdx.x;
    if (e >= NE) return;
    int is64 = g_is64;
    int s = edge_at(raw, e, is64);
    int d = edge_at(raw, NE + e, is64);
    if ((unsigned)s >= NN || (unsigned)d >= NN) return;
    int pos = atomicAdd(&g_cur[d], 1);
    g_edge[pos] = make_int2(s, __float_as_int(g_dinv[s] * g_dinv[d]));
}

// ---------------- GEMM epilogue stores ----------------
__device__ __forceinline__ void store4(float* p, float a, float b, float c, float d) {
    *(float4*)p = make_float4(a, b, c, d);
}
__device__ __forceinline__ void store4(__half* p, float a, float b, float c, float d) {
    *(__half2*)p = __floats2half2_rn(a, b);
    *(__half2*)(p + 2) = __floats2half2_rn(c, d);
}

// ---------------- dense GEMM: out[N,NC] = in[N,64] @ W[64,NC] (+bias) ----------------
template <int NC, typename InT, typename OutT, bool BIAS>
__global__ void __launch_bounds__(256) k_gemm(const InT* __restrict__ in,
                                              const float* __restrict__ W,
                                              const float* __restrict__ bias,
                                              OutT* __restrict__ out) {
    constexpr int CG = NC / 4;       // col groups of 4
    constexpr int RQ = 256 / CG;     // row groups
    constexpr int TM = RQ * 4;       // rows per tile
    constexpr int XP = 65;
    __shared__ float Ws[64 * NC];
    __shared__ float Xs[TM * XP];

    for (int i = threadIdx.x; i < 64 * NC; i += 256) Ws[i] = W[i];

    int rq = threadIdx.x / CG;
    int cg = threadIdx.x % CG;
    int ntiles = (NN + TM - 1) / TM;

    for (int tile = blockIdx.x; tile < ntiles; tile += gridDim.x) {
        int row0 = tile * TM;
        int nr = min(TM, NN - row0);
        __syncthreads();
        if constexpr (sizeof(InT) == 4) {
            const float* src = (const float*)in + row0 * 64;
            for (int i = threadIdx.x; i < nr * 64; i += 256)
                Xs[(i >> 6) * XP + (i & 63)] = src[i];
        } else {
            const __half2* src = (const __half2*)((const __half*)in + row0 * 64);
            for (int i = threadIdx.x; i < nr * 32; i += 256) {
                float2 f = __half22float2(src[i]);
                int r = i >> 5, c = (i & 31) * 2;
                Xs[r * XP + c] = f.x;
                Xs[r * XP + c + 1] = f.y;
            }
        }
        __syncthreads();

        unsigned long long acc[4][2] = {};
#pragma unroll 4
        for (int k = 0; k < 64; k++) {
            ulonglong2 w = *(const ulonglong2*)&Ws[k * NC + cg * 4];
#pragma unroll
            for (int r = 0; r < 4; r++) {
                float xv = Xs[(rq * 4 + r) * XP + k];
                unsigned long long xx;
                PACK_F32X2(xx, xv, xv);
                FMA_F32X2(acc[r][0], xx, w.x, acc[r][0]);
                FMA_F32X2(acc[r][1], xx, w.y, acc[r][1]);
            }
        }
        float4 bv = make_float4(0.f, 0.f, 0.f, 0.f);
        if (BIAS) bv = *(const float4*)&bias[cg * 4];
#pragma unroll
        for (int r = 0; r < 4; r++) {
            int row = row0 + rq * 4 + r;
            if (row < NN) {
                float f0, f1, f2, f3;
                UNPACK_F32X2(f0, f1, acc[r][0]);
                UNPACK_F32X2(f2, f3, acc[r][1]);
                store4(&out[row * NC + cg * 4],
                       f0 + bv.x, f1 + bv.y, f2 + bv.z, f3 + bv.w);
            }
        }
    }
}

// ---------------- aggregate: out[i] = relu( sum_e norm*hw[src] + dinv^2*hw[i] + b ) ----------------
__global__ void __launch_bounds__(256) k_gather(const __half2* __restrict__ hw,
                                                const float* __restrict__ bias,
                                                __half2* __restrict__ hout) {
    int node = blockIdx.x * 8 + (threadIdx.x >> 5);
    if (node >= NN) return;
    int lane = threadIdx.x & 31;

    float di = g_dinv[node];
    float self = di * di;
    float2 v = __half22float2(__ldg(&hw[node * 32 + lane]));
    float ax = self * v.x, ay = self * v.y;

    int beg = g_rowptr[node], end = g_rowptr[node + 1];
    int j = beg;
    for (; j + 4 <= end; j += 4) {
        int2 e0 = __ldg(&g_edge[j]);
        int2 e1 = __ldg(&g_edge[j + 1]);
        int2 e2 = __ldg(&g_edge[j + 2]);
        int2 e3 = __ldg(&g_edge[j + 3]);
        float2 u0 = __half22float2(__ldg(&hw[e0.x * 32 + lane]));
        float2 u1 = __half22float2(__ldg(&hw[e1.x * 32 + lane]));
        float2 u2 = __half22float2(__ldg(&hw[e2.x * 32 + lane]));
        float2 u3 = __half22float2(__ldg(&hw[e3.x * 32 + lane]));
        float w0 = __int_as_float(e0.y), w1 = __int_as_float(e1.y);
        float w2 = __int_as_float(e2.y), w3 = __int_as_float(e3.y);
        ax = fmaf(w0, u0.x, ax); ay = fmaf(w0, u0.y, ay);
        ax = fmaf(w1, u1.x, ax); ay = fmaf(w1, u1.y, ay);
        ax = fmaf(w2, u2.x, ax); ay = fmaf(w2, u2.y, ay);
        ax = fmaf(w3, u3.x, ax); ay = fmaf(w3, u3.y, ay);
    }
    for (; j < end; j++) {
        int2 e = __ldg(&g_edge[j]);
        float2 u = __half22float2(__ldg(&hw[e.x * 32 + lane]));
        float w = __int_as_float(e.y);
        ax = fmaf(w, u.x, ax); ay = fmaf(w, u.y, ay);
    }
    float2 b = ((const float2*)bias)[lane];
    ax = fmaxf(ax + b.x, 0.f);
    ay = fmaxf(ay + b.y, 0.f);
    hout[node * 32 + lane] = __floats2half2_rn(ax, ay);
}

// ---------------- launch ----------------
extern "C" void kernel_launch(void* const* d_in, const int* in_sizes, int n_in,
                              void* d_out, int out_size) {
    const float* x  = (const float*)d_in[0];
    const int*   ei = (const int*)d_in[1];
    const float* W1 = (const float*)d_in[2];
    const float* b1 = (const float*)d_in[3];
    const float* W2 = (const float*)d_in[4];
    const float* b2 = (const float*)d_in[5];
    const float* Wl = (const float*)d_in[6];
    const float* bl = (const float*)d_in[7];
    float*       out = (float*)d_out;

    __half* bufh; cudaGetSymbolAddress((void**)&bufh, g_bufh);
    __half* buf2; cudaGetSymbolAddress((void**)&buf2, g_buf2);

    // side stream + events for fork/join inside capture (host objects only)
    static cudaStream_t s2 = nullptr;
    static cudaEvent_t evFork = nullptr, evJoin = nullptr;
    if (s2 == nullptr) {
        cudaStreamCreateWithFlags(&s2, cudaStreamNonBlocking);
        cudaEventCreateWithFlags(&evFork, cudaEventDisableTiming);
        cudaEventCreateWithFlags(&evJoin, cudaEventDisableTiming);
    }

    const int TB = 256;
    int gN = (NN + TB - 1) / TB;
    int gE = (NE + TB - 1) / TB;
    const int GEMM_GRID = 296;
    const int GATHER_GRID = (NN + 7) / 8;

    // fork: GEMM1 (x @ W1) is independent of the CSR build
    cudaEventRecord(evFork, 0);
    cudaStreamWaitEvent(s2, evFork, 0);
    k_gemm<64, float, __half, false><<<GEMM_GRID, 256, 0, s2>>>(x, W1, nullptr, bufh);
    cudaEventRecord(evJoin, s2);

    // CSR build on the main stream (concurrent with GEMM1)
    k_initdetect<<<gN, TB>>>(ei);
    k_count<<<gE, TB>>>(ei);
    k_scan1<<<SCAN_B, 1024>>>();
    k_scan23<<<SCAN_B, 1024>>>();
    k_fill<<<gE, TB>>>(ei);

    // join: gather1 needs both GEMM1 output and the CSR
    cudaStreamWaitEvent(0, evJoin, 0);
    k_gather<<<GATHER_GRID, 256>>>((const __half2*)bufh, b1, (__half2*)buf2);
    k_gemm<64, __half, __half, false><<<GEMM_GRID, 256>>>(buf2, W2, nullptr, bufh);
    k_gather<<<GATHER_GRID, 256>>>((const __half2*)bufh, b2, (__half2*)buf2);
    k_gemm<32, __half, float, true><<<GEMM_GRID, 256>>>(buf2, Wl, bl, out);
}